// round 12
// baseline (speedup 1.0000x reference)
#include <cuda_runtime.h>
#include <cuda_fp16.h>
#include <cstdint>

// Problem constants
#define B_  4
#define S_  2048
#define C_  1024
#define H_  16
#define D_  64
#define M_  (B_ * S_)      // 8192 tokens

// Scratch (allocation-free rule: __device__ globals)
__device__ __half g_xh  [(size_t)M_ * C_];        // x in fp16
__device__ __half g_wh  [3 * C_ * C_];            // qkv_w fp16
__device__ __half g_pwh [C_ * C_];                // proj_w fp16
__device__ __half g_qkvh[(size_t)M_ * 3 * C_];    // qkv activations fp16
__device__ __half g_atth[(size_t)M_ * C_];        // attention out fp16

// ---------------------------------------------------------------------------
// helpers
// ---------------------------------------------------------------------------
__device__ __forceinline__ uint32_t pack_h2(float x, float y) {
    __half2 h = __floats2half2_rn(x, y);
    return *reinterpret_cast<uint32_t*>(&h);
}

__device__ __forceinline__ uint32_t ex2_h2(uint32_t a) {
    uint32_t d;
    asm("ex2.approx.f16x2 %0, %1;" : "=r"(d) : "r"(a));
    return d;
}

__device__ __forceinline__ void mma_f16(float& c0, float& c1, float& c2, float& c3,
                                        uint32_t a0, uint32_t a1, uint32_t a2, uint32_t a3,
                                        uint32_t b0, uint32_t b1) {
    asm volatile(
        "mma.sync.aligned.m16n8k16.row.col.f32.f16.f16.f32 "
        "{%0,%1,%2,%3}, {%4,%5,%6,%7}, {%8,%9}, {%0,%1,%2,%3};\n"
        : "+f"(c0), "+f"(c1), "+f"(c2), "+f"(c3)
        : "r"(a0), "r"(a1), "r"(a2), "r"(a3), "r"(b0), "r"(b1));
}

__device__ __forceinline__ void ldsm_x4(uint32_t& r0, uint32_t& r1, uint32_t& r2, uint32_t& r3,
                                        uint32_t addr) {
    asm volatile("ldmatrix.sync.aligned.m8n8.x4.shared.b16 {%0,%1,%2,%3}, [%4];\n"
                 : "=r"(r0), "=r"(r1), "=r"(r2), "=r"(r3) : "r"(addr));
}

__device__ __forceinline__ void ldsm_x4_trans(uint32_t& r0, uint32_t& r1, uint32_t& r2, uint32_t& r3,
                                              uint32_t addr) {
    asm volatile("ldmatrix.sync.aligned.m8n8.x4.trans.shared.b16 {%0,%1,%2,%3}, [%4];\n"
                 : "=r"(r0), "=r"(r1), "=r"(r2), "=r"(r3) : "r"(addr));
}

__device__ __forceinline__ void cp16(uint32_t dst, const void* src) {
    asm volatile("cp.async.cg.shared.global [%0], [%1], 16;\n" :: "r"(dst), "l"(src));
}

#define CP_COMMIT() asm volatile("cp.async.commit_group;" ::: "memory")
#define CP_WAIT(n)  asm volatile("cp.async.wait_group %0;" :: "n"(n) : "memory")

// ---------------------------------------------------------------------------
// merged f32 -> f16 conversion (3 segments, one launch; 8 elems/thread)
// ---------------------------------------------------------------------------
struct F2HArgs {
    const float* s0; __half* d0; int n0;
    const float* s1; __half* d1; int n1;
    const float* s2; __half* d2; int n2;
};

__device__ __forceinline__ void cvt8(const float* s, __half* d, int i) {
    float4 a = *(const float4*)(s + i);
    float4 b = *(const float4*)(s + i + 4);
    uint4 o;
    o.x = pack_h2(a.x, a.y);
    o.y = pack_h2(a.z, a.w);
    o.z = pack_h2(b.x, b.y);
    o.w = pack_h2(b.z, b.w);
    *(uint4*)(d + i) = o;
}

__global__ __launch_bounds__(256) void f2h_all(F2HArgs a) {
    int i = (blockIdx.x * 256 + threadIdx.x) * 8;
    if (i < a.n0) { cvt8(a.s0, a.d0, i); return; }
    i -= a.n0;
    if (i < a.n1) { cvt8(a.s1, a.d1, i); return; }
    i -= a.n1;
    if (i < a.n2) { cvt8(a.s2, a.d2, i); }
}

// ---------------------------------------------------------------------------
// HMMA GEMM — R6 config (best measured). CTA 128x128, 4 warps (2x2),
// warp tile 64x64, K-slab 32, double buffer.
// ---------------------------------------------------------------------------
template<typename OutT>
__global__ __launch_bounds__(128, 2) void gemm_hmma(
    const __half* __restrict__ A, const __half* __restrict__ W,
    const float* __restrict__ bias, OutT* __restrict__ Cmat, int N)
{
    __shared__ __half As[2][128][40];
    __shared__ __half Bs[2][128][40];

    const int tid  = threadIdx.x;
    const int lane = tid & 31;
    const int w    = tid >> 5;
    const int m_off = (w >> 1) * 64;
    const int n_off = (w & 1) * 64;
    const int brow = blockIdx.y * 128;
    const int bcol = blockIdx.x * 128;

    const int gr = lane >> 2;
    const int gc = lane & 3;
    const int lrow8 = ((lane >> 3) & 1) * 8 + (lane & 7);
    const int lhi8  = ((lane >> 4) & 1) * 8;
    const uint32_t as0 = (uint32_t)__cvta_generic_to_shared(&As[0][0][0]);
    const uint32_t bs0 = (uint32_t)__cvta_generic_to_shared(&Bs[0][0][0]);

    float acc[4][8][4];
#pragma unroll
    for (int a = 0; a < 4; a++)
#pragma unroll
        for (int n = 0; n < 8; n++)
#pragma unroll
            for (int c = 0; c < 4; c++) acc[a][n][c] = 0.f;

    auto load_slab = [&](int k0, int s) {
#pragma unroll
        for (int i = 0; i < 4; i++) {
            int idx = i * 128 + tid;
            int rr = idx >> 2;
            int cc = (idx & 3) * 8;
            cp16(as0 + (uint32_t)(((s * 128 + rr) * 40 + cc) * 2),
                 A + (size_t)(brow + rr) * 1024 + k0 + cc);
            cp16(bs0 + (uint32_t)(((s * 128 + rr) * 40 + cc) * 2),
                 W + (size_t)(bcol + rr) * 1024 + k0 + cc);
        }
    };

    load_slab(0, 0);
    CP_COMMIT();

    for (int k = 0; k < 32; k++) {
        const int buf = k & 1;
        if (k + 1 < 32) {
            load_slab((k + 1) * 32, (k + 1) & 1);
            CP_COMMIT();
            CP_WAIT(1);
        } else {
            CP_WAIT(0);
        }
        __syncthreads();

#pragma unroll
        for (int kk = 0; kk < 2; kk++) {
            uint32_t af[4][4];
#pragma unroll
            for (int a = 0; a < 4; a++) {
                uint32_t addr = as0 +
                    (uint32_t)(((buf * 128 + m_off + 16 * a + lrow8) * 40 + kk * 16 + lhi8) * 2);
                ldsm_x4(af[a][0], af[a][1], af[a][2], af[a][3], addr);
            }
            uint32_t bf[8][2];
#pragma unroll
            for (int c = 0; c < 4; c++) {
                int nrow = n_off + c * 16 + lhi8 + (lane & 7);
                int kcol = kk * 16 + ((lane >> 3) & 1) * 8;
                uint32_t addr = bs0 + (uint32_t)(((buf * 128 + nrow) * 40 + kcol) * 2);
                ldsm_x4(bf[2 * c][0], bf[2 * c][1], bf[2 * c + 1][0], bf[2 * c + 1][1], addr);
            }
#pragma unroll
            for (int a = 0; a < 4; a++)
#pragma unroll
                for (int n = 0; n < 8; n++)
                    mma_f16(acc[a][n][0], acc[a][n][1], acc[a][n][2], acc[a][n][3],
                            af[a][0], af[a][1], af[a][2], af[a][3],
                            bf[n][0], bf[n][1]);
        }
        __syncthreads();
    }

#pragma unroll
    for (int a = 0; a < 4; a++) {
        int r0 = brow + m_off + 16 * a + gr;
#pragma unroll
        for (int n = 0; n < 8; n++) {
            int col = bcol + n_off + 8 * n + 2 * gc;
            float b0 = bias[col], b1 = bias[col + 1];
            if constexpr (sizeof(OutT) == 4) {
                float* p0 = (float*)Cmat + (size_t)r0 * N + col;
                float* p1 = (float*)Cmat + (size_t)(r0 + 8) * N + col;
                float2 o0, o1;
                o0.x = acc[a][n][0] + b0; o0.y = acc[a][n][1] + b1;
                o1.x = acc[a][n][2] + b0; o1.y = acc[a][n][3] + b1;
                *(float2*)p0 = o0;
                *(float2*)p1 = o1;
            } else {
                __half* p0 = (__half*)Cmat + (size_t)r0 * N + col;
                __half* p1 = (__half*)Cmat + (size_t)(r0 + 8) * N + col;
                *(uint32_t*)p0 = pack_h2(acc[a][n][0] + b0, acc[a][n][1] + b1);
                *(uint32_t*)p1 = pack_h2(acc[a][n][2] + b0, acc[a][n][3] + b1);
            }
        }
    }
}

// ---------------------------------------------------------------------------
// Flash attention (causal), fp16 in/out, log2-domain softmax.
// R12: __launch_bounds__(128, 3) — cap regs (~170) so 3 CTAs/SM fit
// (smem 73.7KB x 3 = 221KB < 228KB). +50% warps/SMSP for latency cover.
// Ping-pong KV smem, deferred per-lane l, packed-h2 max reduce.
// ---------------------------------------------------------------------------
__global__ __launch_bounds__(128, 3) void attn_f16(
    const __half* __restrict__ qkv, __half* __restrict__ out)
{
    extern __shared__ __half sm[];          // Ks[2][64][72] | Vs[2][64][72]
    __half* KsP = sm;
    __half* VsP = sm + 2 * 64 * 72;
    const uint32_t ks0 = (uint32_t)__cvta_generic_to_shared(KsP);
    const uint32_t vs0 = (uint32_t)__cvta_generic_to_shared(VsP);
    const uint32_t BUFB = 64 * 72 * 2;      // buffer stride in bytes

    const int qblk = gridDim.x - 1 - blockIdx.x;   // heavy blocks first
    const int bh   = blockIdx.y;
    const int b    = bh >> 4;
    const int h    = bh & 15;

    const int tid  = threadIdx.x;
    const int lane = tid & 31;
    const int w    = tid >> 5;
    const int gr   = lane >> 2;
    const int gc   = lane & 3;
    const int lrow8 = ((lane >> 3) & 1) * 8 + (lane & 7);
    const int lhi8  = ((lane >> 4) & 1) * 8;

    const __half* base = qkv + (size_t)b * S_ * 3 * C_;

    // ---- Q prologue: two 64-row phases through Ks buf0; hoist+scale frags ----
    const __half2 qscale = __float2half2_rn(0.1803368801f);   // 0.125 * log2(e)
    uint32_t qf[2][4][4];
#pragma unroll
    for (int p = 0; p < 2; p++) {
#pragma unroll
        for (int i = 0; i < 4; i++) {
            int idx = i * 128 + tid;
            int r = idx >> 3;
            int c8 = (idx & 7) * 8;
            *(uint4*)&KsP[r * 72 + c8] = *(const uint4*)(
                base + (size_t)(qblk * 128 + p * 64 + r) * (3 * C_) + h * 64 + c8);
        }
        __syncthreads();
        if ((w >> 1) == p) {
            int lr = (w & 1) * 32;
#pragma unroll
            for (int mi = 0; mi < 2; mi++)
#pragma unroll
                for (int kk = 0; kk < 4; kk++) {
                    uint32_t addr = ks0 +
                        ((uint32_t)(lr + 16 * mi + lrow8) * 72u + kk * 16 + lhi8) * 2u;
                    ldsm_x4(qf[mi][kk][0], qf[mi][kk][1], qf[mi][kk][2], qf[mi][kk][3], addr);
#pragma unroll
                    for (int i = 0; i < 4; i++) {
                        __half2 v = *reinterpret_cast<__half2*>(&qf[mi][kk][i]);
                        v = __hmul2(v, qscale);
                        qf[mi][kk][i] = *reinterpret_cast<uint32_t*>(&v);
                    }
                }
        }
        __syncthreads();
    }

    float o[2][8][4];
#pragma unroll
    for (int mi = 0; mi < 2; mi++)
#pragma unroll
        for (int j = 0; j < 8; j++)
#pragma unroll
            for (int c = 0; c < 4; c++) o[mi][j][c] = 0.f;
    float mm[2][2] = {{-1e30f, -1e30f}, {-1e30f, -1e30f}};
    float ll[2][2] = {{0.f, 0.f}, {0.f, 0.f}};   // PER-LANE partials

    const int nkv = 2 * qblk + 2;

    // ---- load tile 0 into buf 0 ----
#pragma unroll
    for (int i = 0; i < 4; i++) {
        int idx = i * 128 + tid;
        int r = idx >> 3;
        int c8 = (idx & 7) * 8;
        *(uint4*)&KsP[r * 72 + c8] =
            *(const uint4*)(base + (size_t)r * (3 * C_) + C_ + h * 64 + c8);
        *(uint4*)&VsP[r * 72 + c8] =
            *(const uint4*)(base + (size_t)r * (3 * C_) + 2 * C_ + h * 64 + c8);
    }
    __syncthreads();

    for (int kvb = 0; kvb < nkv; kvb++) {
        const int buf = kvb & 1;
        const bool more = (kvb + 1 < nkv);

        // issue next tile's loads early (latency overlaps compute below)
        uint4 kreg[4], vreg[4];
        if (more) {
#pragma unroll
            for (int i = 0; i < 4; i++) {
                int idx = i * 128 + tid;
                int r = idx >> 3;
                int c8 = (idx & 7) * 8;
                const __half* rowp = base + (size_t)((kvb + 1) * 64 + r) * (3 * C_) + h * 64 + c8;
                kreg[i] = *(const uint4*)(rowp + C_);
                vreg[i] = *(const uint4*)(rowp + 2 * C_);
            }
        }

        const uint32_t kbase = ks0 + (uint32_t)buf * BUFB;
        const uint32_t vbase = vs0 + (uint32_t)buf * BUFB;

        // ---- S = Q K^T (log2 domain) ----
        float s[2][8][4];
#pragma unroll
        for (int mi = 0; mi < 2; mi++)
#pragma unroll
            for (int j = 0; j < 8; j++)
#pragma unroll
                for (int c = 0; c < 4; c++) s[mi][j][c] = 0.f;

#pragma unroll
        for (int kk = 0; kk < 4; kk++) {
#pragma unroll
            for (int c = 0; c < 4; c++) {
                int nrow = c * 16 + lhi8 + (lane & 7);
                int kcol = kk * 16 + ((lane >> 3) & 1) * 8;
                uint32_t addr = kbase + ((uint32_t)nrow * 72u + kcol) * 2u;
                uint32_t b00, b01, b10, b11;
                ldsm_x4(b00, b01, b10, b11, addr);
#pragma unroll
                for (int mi = 0; mi < 2; mi++) {
                    mma_f16(s[mi][2 * c][0], s[mi][2 * c][1], s[mi][2 * c][2], s[mi][2 * c][3],
                            qf[mi][kk][0], qf[mi][kk][1], qf[mi][kk][2], qf[mi][kk][3], b00, b01);
                    mma_f16(s[mi][2 * c + 1][0], s[mi][2 * c + 1][1],
                            s[mi][2 * c + 1][2], s[mi][2 * c + 1][3],
                            qf[mi][kk][0], qf[mi][kk][1], qf[mi][kk][2], qf[mi][kk][3], b10, b11);
                }
            }
        }

        // ---- causal mask (last two kv tiles only) ----
        if (kvb >= 2 * qblk) {
#pragma unroll
            for (int mi = 0; mi < 2; mi++) {
                int rowm = qblk * 128 + 32 * w + 16 * mi + gr;
#pragma unroll
                for (int j = 0; j < 8; j++) {
                    int colb = kvb * 64 + 8 * j + 2 * gc;
                    if (colb     > rowm)     s[mi][j][0] = -1e30f;
                    if (colb + 1 > rowm)     s[mi][j][1] = -1e30f;
                    if (colb     > rowm + 8) s[mi][j][2] = -1e30f;
                    if (colb + 1 > rowm + 8) s[mi][j][3] = -1e30f;
                }
            }
        }

        // ---- online softmax (log2 domain); l kept per-lane ----
        uint32_t ph[2][8][2];
#pragma unroll
        for (int mi = 0; mi < 2; mi++) {
            float mt0 = -1e30f, mt1 = -1e30f;
#pragma unroll
            for (int j = 0; j < 8; j++) {
                mt0 = fmaxf(mt0, fmaxf(s[mi][j][0], s[mi][j][1]));
                mt1 = fmaxf(mt1, fmaxf(s[mi][j][2], s[mi][j][3]));
            }
            // packed half2 quad-reduce of (mt0, mt1)
            {
                uint32_t mp = pack_h2(mt0, mt1);
                __half2 hv = *reinterpret_cast<__half2*>(&mp);
                uint32_t r1 = __shfl_xor_sync(0xffffffffu, mp, 1);
                hv = __hmax2(hv, *reinterpret_cast<__half2*>(&r1));
                uint32_t mp2 = *reinterpret_cast<uint32_t*>(&hv);
                uint32_t r2 = __shfl_xor_sync(0xffffffffu, mp2, 2);
                hv = __hmax2(hv, *reinterpret_cast<__half2*>(&r2));
                mt0 = __low2float(hv);
                mt1 = __high2float(hv);
            }

            const float mn0 = fmaxf(mm[mi][0], mt0);
            const float mn1 = fmaxf(mm[mi][1], mt1);
            float ls0 = 0.f, ls1 = 0.f;
#pragma unroll
            for (int j = 0; j < 8; j++) {
                uint32_t h0 = ex2_h2(pack_h2(s[mi][j][0] - mn0, s[mi][j][1] - mn0));
                uint32_t h1 = ex2_h2(pack_h2(s[mi][j][2] - mn1, s[mi][j][3] - mn1));
                ph[mi][j][0] = h0;
                ph[mi][j][1] = h1;
                float2 f0 = __half22float2(*reinterpret_cast<__half2*>(&h0));
                float2 f1 = __half22float2(*reinterpret_cast<__half2*>(&h1));
                ls0 += f0.x + f0.y;
                ls1 += f1.x + f1.y;
            }

            // warp-voted rescale skip; l stays per-lane (no shuffles here)
            bool no_rescale = (mn0 == mm[mi][0]) && (mn1 == mm[mi][1]);
            if (__all_sync(0xffffffffu, no_rescale)) {
                ll[mi][0] += ls0;
                ll[mi][1] += ls1;
            } else {
                const float al0 = exp2f(mm[mi][0] - mn0);
                const float al1 = exp2f(mm[mi][1] - mn1);
                ll[mi][0] = ll[mi][0] * al0 + ls0;
                ll[mi][1] = ll[mi][1] * al1 + ls1;
                mm[mi][0] = mn0;
                mm[mi][1] = mn1;
#pragma unroll
                for (int j = 0; j < 8; j++) {
                    o[mi][j][0] *= al0; o[mi][j][1] *= al0;
                    o[mi][j][2] *= al1; o[mi][j][3] *= al1;
                }
            }
        }

        // ---- PV: ph pairs ARE the fp16 A-frags ----
#pragma unroll
        for (int kk = 0; kk < 4; kk++) {
#pragma unroll
            for (int c = 0; c < 4; c++) {
                int kvrow = kk * 16 + ((lane >> 3) & 1) * 8 + (lane & 7);
                int dcol  = c * 16 + lhi8;
                uint32_t addr = vbase + ((uint32_t)kvrow * 72u + dcol) * 2u;
                uint32_t b00, b01, b10, b11;
                ldsm_x4_trans(b00, b01, b10, b11, addr);
#pragma unroll
                for (int mi = 0; mi < 2; mi++) {
                    mma_f16(o[mi][2 * c][0], o[mi][2 * c][1], o[mi][2 * c][2], o[mi][2 * c][3],
                            ph[mi][2 * kk][0], ph[mi][2 * kk][1],
                            ph[mi][2 * kk + 1][0], ph[mi][2 * kk + 1][1], b00, b01);
                    mma_f16(o[mi][2 * c + 1][0], o[mi][2 * c + 1][1],
                            o[mi][2 * c + 1][2], o[mi][2 * c + 1][3],
                            ph[mi][2 * kk][0], ph[mi][2 * kk][1],
                            ph[mi][2 * kk + 1][0], ph[mi][2 * kk + 1][1], b10, b11);
                }
            }
        }

        // ---- stage next tile into the other buffer; single barrier ----
        if (more) {
            const int nb = buf ^ 1;
#pragma unroll
            for (int i = 0; i < 4; i++) {
                int idx = i * 128 + tid;
                int r = idx >> 3;
                int c8 = (idx & 7) * 8;
                *(uint4*)&KsP[nb * 64 * 72 + r * 72 + c8] = kreg[i];
                *(uint4*)&VsP[nb * 64 * 72 + r * 72 + c8] = vreg[i];
            }
        }
        __syncthreads();
    }

    // ---- final l quad-reduction + normalize + write fp16 ----
#pragma unroll
    for (int mi = 0; mi < 2; mi++) {
        float l0 = ll[mi][0], l1 = ll[mi][1];
        l0 += __shfl_xor_sync(0xffffffffu, l0, 1);
        l0 += __shfl_xor_sync(0xffffffffu, l0, 2);
        l1 += __shfl_xor_sync(0xffffffffu, l1, 1);
        l1 += __shfl_xor_sync(0xffffffffu, l1, 2);
        const float il0 = 1.f / l0;
        const float il1 = 1.f / l1;
        const int row0 = qblk * 128 + 32 * w + 16 * mi + gr;
        __half* op0 = out + (size_t)(b * S_ + row0) * C_ + h * 64;
        __half* op1 = out + (size_t)(b * S_ + row0 + 8) * C_ + h * 64;
#pragma unroll
        for (int j2 = 0; j2 < 8; j2++) {
            int d0 = 8 * j2 + 2 * gc;
            *(uint32_t*)&op0[d0] = pack_h2(o[mi][j2][0] * il0, o[mi][j2][1] * il0);
            *(uint32_t*)&op1[d0] = pack_h2(o[mi][j2][2] * il1, o[mi][j2][3] * il1);
        }
    }
}

// ---------------------------------------------------------------------------
extern "C" void kernel_launch(void* const* d_in, const int* in_sizes, int n_in,
                              void* d_out, int out_size)
{
    const float* x      = (const float*)d_in[0];
    const float* qkv_w  = (const float*)d_in[1];
    const float* qkv_b  = (const float*)d_in[2];
    const float* proj_w = (const float*)d_in[3];
    const float* proj_b = (const float*)d_in[4];
    float* out = (float*)d_out;

    __half *xh, *wh, *pwh, *qkvh, *atth;
    cudaGetSymbolAddress((void**)&xh,   g_xh);
    cudaGetSymbolAddress((void**)&wh,   g_wh);
    cudaGetSymbolAddress((void**)&pwh,  g_pwh);
    cudaGetSymbolAddress((void**)&qkvh, g_qkvh);
    cudaGetSymbolAddress((void**)&atth, g_atth);

    const int ASM = 4 * 64 * 72 * 2;   // 73,728 B (ping-pong K+V)
    cudaFuncSetAttribute((const void*)attn_f16,
                         cudaFuncAttributeMaxDynamicSharedMemorySize, ASM);

    // merged fp16 conversion (one launch)
    F2HArgs fa;
    fa.s0 = x;      fa.d0 = xh;  fa.n0 = M_ * C_;
    fa.s1 = qkv_w;  fa.d1 = wh;  fa.n1 = 3 * C_ * C_;
    fa.s2 = proj_w; fa.d2 = pwh; fa.n2 = C_ * C_;
    const int total = fa.n0 + fa.n1 + fa.n2;
    f2h_all<<<total / 2048, 256>>>(fa);

    // QKV: [8192,1024] x [3072,1024]^T -> fp16
    gemm_hmma<__half><<<dim3(3072 / 128, M_ / 128), 128>>>(xh, wh, qkv_b, qkvh, 3 * C_);
    // Attention (fp16 in/out), Q tile 128, ping-pong KV, 3 CTA/SM
    attn_f16<<<dim3(S_ / 128, B_ * H_), 128, ASM>>>(qkvh, atth);
    // Proj: [8192,1024] x [1024,1024]^T -> fp32 out
    gemm_hmma<float><<<dim3(C_ / 128, M_ / 128), 128>>>(atth, pwh, proj_b, out, C_);
}

// round 13
// speedup vs baseline: 1.4610x; 1.4610x over previous
#include <cuda_runtime.h>
#include <cuda_fp16.h>
#include <cstdint>

// Problem constants
#define B_  4
#define S_  2048
#define C_  1024
#define H_  16
#define D_  64
#define M_  (B_ * S_)      // 8192 tokens

// Scratch (allocation-free rule: __device__ globals)
__device__ __half g_xh  [(size_t)M_ * C_];        // x in fp16
__device__ __half g_wh  [3 * C_ * C_];            // qkv_w fp16
__device__ __half g_pwh [C_ * C_];                // proj_w fp16
__device__ __half g_qkvh[(size_t)M_ * 3 * C_];    // qkv activations fp16
__device__ __half g_atth[(size_t)M_ * C_];        // attention out fp16

// ---------------------------------------------------------------------------
// helpers
// ---------------------------------------------------------------------------
__device__ __forceinline__ uint32_t pack_h2(float x, float y) {
    __half2 h = __floats2half2_rn(x, y);
    return *reinterpret_cast<uint32_t*>(&h);
}

__device__ __forceinline__ uint32_t ex2_h2(uint32_t a) {
    uint32_t d;
    asm("ex2.approx.f16x2 %0, %1;" : "=r"(d) : "r"(a));
    return d;
}

__device__ __forceinline__ void mma_f16(float& c0, float& c1, float& c2, float& c3,
                                        uint32_t a0, uint32_t a1, uint32_t a2, uint32_t a3,
                                        uint32_t b0, uint32_t b1) {
    asm volatile(
        "mma.sync.aligned.m16n8k16.row.col.f32.f16.f16.f32 "
        "{%0,%1,%2,%3}, {%4,%5,%6,%7}, {%8,%9}, {%0,%1,%2,%3};\n"
        : "+f"(c0), "+f"(c1), "+f"(c2), "+f"(c3)
        : "r"(a0), "r"(a1), "r"(a2), "r"(a3), "r"(b0), "r"(b1));
}

__device__ __forceinline__ void ldsm_x4(uint32_t& r0, uint32_t& r1, uint32_t& r2, uint32_t& r3,
                                        uint32_t addr) {
    asm volatile("ldmatrix.sync.aligned.m8n8.x4.shared.b16 {%0,%1,%2,%3}, [%4];\n"
                 : "=r"(r0), "=r"(r1), "=r"(r2), "=r"(r3) : "r"(addr));
}

__device__ __forceinline__ void ldsm_x4_trans(uint32_t& r0, uint32_t& r1, uint32_t& r2, uint32_t& r3,
                                              uint32_t addr) {
    asm volatile("ldmatrix.sync.aligned.m8n8.x4.trans.shared.b16 {%0,%1,%2,%3}, [%4];\n"
                 : "=r"(r0), "=r"(r1), "=r"(r2), "=r"(r3) : "r"(addr));
}

__device__ __forceinline__ void cp16(uint32_t dst, const void* src) {
    asm volatile("cp.async.cg.shared.global [%0], [%1], 16;\n" :: "r"(dst), "l"(src));
}

#define CP_COMMIT() asm volatile("cp.async.commit_group;" ::: "memory")
#define CP_WAIT(n)  asm volatile("cp.async.wait_group %0;" :: "n"(n) : "memory")

// ---------------------------------------------------------------------------
// merged f32 -> f16 conversion (3 segments, one launch; 8 elems/thread)
// ---------------------------------------------------------------------------
struct F2HArgs {
    const float* s0; __half* d0; int n0;
    const float* s1; __half* d1; int n1;
    const float* s2; __half* d2; int n2;
};

__device__ __forceinline__ void cvt8(const float* s, __half* d, int i) {
    float4 a = *(const float4*)(s + i);
    float4 b = *(const float4*)(s + i + 4);
    uint4 o;
    o.x = pack_h2(a.x, a.y);
    o.y = pack_h2(a.z, a.w);
    o.z = pack_h2(b.x, b.y);
    o.w = pack_h2(b.z, b.w);
    *(uint4*)(d + i) = o;
}

__global__ __launch_bounds__(256) void f2h_all(F2HArgs a) {
    int i = (blockIdx.x * 256 + threadIdx.x) * 8;
    if (i < a.n0) { cvt8(a.s0, a.d0, i); return; }
    i -= a.n0;
    if (i < a.n1) { cvt8(a.s1, a.d1, i); return; }
    i -= a.n1;
    if (i < a.n2) { cvt8(a.s2, a.d2, i); }
}

// ---------------------------------------------------------------------------
// HMMA GEMM — R6 config (best measured). CTA 128x128, 4 warps (2x2),
// warp tile 64x64, K-slab 32, double buffer.
// ---------------------------------------------------------------------------
template<typename OutT>
__global__ __launch_bounds__(128, 2) void gemm_hmma(
    const __half* __restrict__ A, const __half* __restrict__ W,
    const float* __restrict__ bias, OutT* __restrict__ Cmat, int N)
{
    __shared__ __half As[2][128][40];
    __shared__ __half Bs[2][128][40];

    const int tid  = threadIdx.x;
    const int lane = tid & 31;
    const int w    = tid >> 5;
    const int m_off = (w >> 1) * 64;
    const int n_off = (w & 1) * 64;
    const int brow = blockIdx.y * 128;
    const int bcol = blockIdx.x * 128;

    const int gr = lane >> 2;
    const int gc = lane & 3;
    const int lrow8 = ((lane >> 3) & 1) * 8 + (lane & 7);
    const int lhi8  = ((lane >> 4) & 1) * 8;
    const uint32_t as0 = (uint32_t)__cvta_generic_to_shared(&As[0][0][0]);
    const uint32_t bs0 = (uint32_t)__cvta_generic_to_shared(&Bs[0][0][0]);

    float acc[4][8][4];
#pragma unroll
    for (int a = 0; a < 4; a++)
#pragma unroll
        for (int n = 0; n < 8; n++)
#pragma unroll
            for (int c = 0; c < 4; c++) acc[a][n][c] = 0.f;

    auto load_slab = [&](int k0, int s) {
#pragma unroll
        for (int i = 0; i < 4; i++) {
            int idx = i * 128 + tid;
            int rr = idx >> 2;
            int cc = (idx & 3) * 8;
            cp16(as0 + (uint32_t)(((s * 128 + rr) * 40 + cc) * 2),
                 A + (size_t)(brow + rr) * 1024 + k0 + cc);
            cp16(bs0 + (uint32_t)(((s * 128 + rr) * 40 + cc) * 2),
                 W + (size_t)(bcol + rr) * 1024 + k0 + cc);
        }
    };

    load_slab(0, 0);
    CP_COMMIT();

    for (int k = 0; k < 32; k++) {
        const int buf = k & 1;
        if (k + 1 < 32) {
            load_slab((k + 1) * 32, (k + 1) & 1);
            CP_COMMIT();
            CP_WAIT(1);
        } else {
            CP_WAIT(0);
        }
        __syncthreads();

#pragma unroll
        for (int kk = 0; kk < 2; kk++) {
            uint32_t af[4][4];
#pragma unroll
            for (int a = 0; a < 4; a++) {
                uint32_t addr = as0 +
                    (uint32_t)(((buf * 128 + m_off + 16 * a + lrow8) * 40 + kk * 16 + lhi8) * 2);
                ldsm_x4(af[a][0], af[a][1], af[a][2], af[a][3], addr);
            }
            uint32_t bf[8][2];
#pragma unroll
            for (int c = 0; c < 4; c++) {
                int nrow = n_off + c * 16 + lhi8 + (lane & 7);
                int kcol = kk * 16 + ((lane >> 3) & 1) * 8;
                uint32_t addr = bs0 + (uint32_t)(((buf * 128 + nrow) * 40 + kcol) * 2);
                ldsm_x4(bf[2 * c][0], bf[2 * c][1], bf[2 * c + 1][0], bf[2 * c + 1][1], addr);
            }
#pragma unroll
            for (int a = 0; a < 4; a++)
#pragma unroll
                for (int n = 0; n < 8; n++)
                    mma_f16(acc[a][n][0], acc[a][n][1], acc[a][n][2], acc[a][n][3],
                            af[a][0], af[a][1], af[a][2], af[a][3],
                            bf[n][0], bf[n][1]);
        }
        __syncthreads();
    }

#pragma unroll
    for (int a = 0; a < 4; a++) {
        int r0 = brow + m_off + 16 * a + gr;
#pragma unroll
        for (int n = 0; n < 8; n++) {
            int col = bcol + n_off + 8 * n + 2 * gc;
            float b0 = bias[col], b1 = bias[col + 1];
            if constexpr (sizeof(OutT) == 4) {
                float* p0 = (float*)Cmat + (size_t)r0 * N + col;
                float* p1 = (float*)Cmat + (size_t)(r0 + 8) * N + col;
                float2 o0, o1;
                o0.x = acc[a][n][0] + b0; o0.y = acc[a][n][1] + b1;
                o1.x = acc[a][n][2] + b0; o1.y = acc[a][n][3] + b1;
                *(float2*)p0 = o0;
                *(float2*)p1 = o1;
            } else {
                __half* p0 = (__half*)Cmat + (size_t)r0 * N + col;
                __half* p1 = (__half*)Cmat + (size_t)(r0 + 8) * N + col;
                *(uint32_t*)p0 = pack_h2(acc[a][n][0] + b0, acc[a][n][1] + b1);
                *(uint32_t*)p1 = pack_h2(acc[a][n][2] + b0, acc[a][n][3] + b1);
            }
        }
    }
}

// ---------------------------------------------------------------------------
// Flash attention (causal), fp16 in/out, log2-domain softmax.
// R13: cp.async KV staging into ping-pong buffer (frees ~32 live regs vs
// register staging; min-blocks 2 is a floor — 3 CTAs/SM possible if regs
// drop enough, with NO spill risk). Deferred per-lane l, packed-h2 max.
// Grid (16, 64), block 128; warp w rows 32w..32w+31.
// ---------------------------------------------------------------------------
__global__ __launch_bounds__(128, 2) void attn_f16(
    const __half* __restrict__ qkv, __half* __restrict__ out)
{
    extern __shared__ __half sm[];          // Ks[2][64][72] | Vs[2][64][72]
    __half* KsP = sm;
    __half* VsP = sm + 2 * 64 * 72;
    const uint32_t ks0 = (uint32_t)__cvta_generic_to_shared(KsP);
    const uint32_t vs0 = (uint32_t)__cvta_generic_to_shared(VsP);
    const uint32_t BUFB = 64 * 72 * 2;      // buffer stride in bytes

    const int qblk = gridDim.x - 1 - blockIdx.x;   // heavy blocks first
    const int bh   = blockIdx.y;
    const int b    = bh >> 4;
    const int h    = bh & 15;

    const int tid  = threadIdx.x;
    const int lane = tid & 31;
    const int w    = tid >> 5;
    const int gr   = lane >> 2;
    const int gc   = lane & 3;
    const int lrow8 = ((lane >> 3) & 1) * 8 + (lane & 7);
    const int lhi8  = ((lane >> 4) & 1) * 8;

    const __half* base = qkv + (size_t)b * S_ * 3 * C_;

    // per-thread loader coords (shared by all KV stage calls)
    const int ldr  = tid >> 3;              // 0..15 row group
    const int ldc8 = (tid & 7) * 8;         // 0..56 col

    // ---- Q prologue: two 64-row phases through Ks buf0; hoist+scale frags ----
    const __half2 qscale = __float2half2_rn(0.1803368801f);   // 0.125 * log2(e)
    uint32_t qf[2][4][4];
#pragma unroll
    for (int p = 0; p < 2; p++) {
#pragma unroll
        for (int i = 0; i < 4; i++) {
            int r = i * 16 + ldr;
            *(uint4*)&KsP[r * 72 + ldc8] = *(const uint4*)(
                base + (size_t)(qblk * 128 + p * 64 + r) * (3 * C_) + h * 64 + ldc8);
        }
        __syncthreads();
        if ((w >> 1) == p) {
            int lr = (w & 1) * 32;
#pragma unroll
            for (int mi = 0; mi < 2; mi++)
#pragma unroll
                for (int kk = 0; kk < 4; kk++) {
                    uint32_t addr = ks0 +
                        ((uint32_t)(lr + 16 * mi + lrow8) * 72u + kk * 16 + lhi8) * 2u;
                    ldsm_x4(qf[mi][kk][0], qf[mi][kk][1], qf[mi][kk][2], qf[mi][kk][3], addr);
#pragma unroll
                    for (int i = 0; i < 4; i++) {
                        __half2 v = *reinterpret_cast<__half2*>(&qf[mi][kk][i]);
                        v = __hmul2(v, qscale);
                        qf[mi][kk][i] = *reinterpret_cast<uint32_t*>(&v);
                    }
                }
        }
        __syncthreads();
    }

    float o[2][8][4];
#pragma unroll
    for (int mi = 0; mi < 2; mi++)
#pragma unroll
        for (int j = 0; j < 8; j++)
#pragma unroll
            for (int c = 0; c < 4; c++) o[mi][j][c] = 0.f;
    float mm[2][2] = {{-1e30f, -1e30f}, {-1e30f, -1e30f}};
    float ll[2][2] = {{0.f, 0.f}, {0.f, 0.f}};   // PER-LANE partials

    const int nkv = 2 * qblk + 2;

    // KV stage loader: cp.async K,V (64x64 halves each) into buffer s
    auto stage_kv = [&](int kvb, int s) {
#pragma unroll
        for (int i = 0; i < 4; i++) {
            int r = i * 16 + ldr;
            const __half* rowp = base + (size_t)(kvb * 64 + r) * (3 * C_) + h * 64 + ldc8;
            cp16(ks0 + (uint32_t)s * BUFB + ((uint32_t)r * 72u + ldc8) * 2u, rowp + C_);
            cp16(vs0 + (uint32_t)s * BUFB + ((uint32_t)r * 72u + ldc8) * 2u, rowp + 2 * C_);
        }
    };

    // ---- stage tile 0 into buf 0 ----
    stage_kv(0, 0);
    CP_COMMIT();
    CP_WAIT(0);
    __syncthreads();

    for (int kvb = 0; kvb < nkv; kvb++) {
        const int buf = kvb & 1;

        // stage next tile into the other buffer (sealed by last iter's barrier)
        if (kvb + 1 < nkv) stage_kv(kvb + 1, buf ^ 1);
        CP_COMMIT();

        const uint32_t kbase = ks0 + (uint32_t)buf * BUFB;
        const uint32_t vbase = vs0 + (uint32_t)buf * BUFB;

        // ---- S = Q K^T (log2 domain) ----
        float s[2][8][4];
#pragma unroll
        for (int mi = 0; mi < 2; mi++)
#pragma unroll
            for (int j = 0; j < 8; j++)
#pragma unroll
                for (int c = 0; c < 4; c++) s[mi][j][c] = 0.f;

#pragma unroll
        for (int kk = 0; kk < 4; kk++) {
#pragma unroll
            for (int c = 0; c < 4; c++) {
                int nrow = c * 16 + lhi8 + (lane & 7);
                int kcol = kk * 16 + ((lane >> 3) & 1) * 8;
                uint32_t addr = kbase + ((uint32_t)nrow * 72u + kcol) * 2u;
                uint32_t b00, b01, b10, b11;
                ldsm_x4(b00, b01, b10, b11, addr);
#pragma unroll
                for (int mi = 0; mi < 2; mi++) {
                    mma_f16(s[mi][2 * c][0], s[mi][2 * c][1], s[mi][2 * c][2], s[mi][2 * c][3],
                            qf[mi][kk][0], qf[mi][kk][1], qf[mi][kk][2], qf[mi][kk][3], b00, b01);
                    mma_f16(s[mi][2 * c + 1][0], s[mi][2 * c + 1][1],
                            s[mi][2 * c + 1][2], s[mi][2 * c + 1][3],
                            qf[mi][kk][0], qf[mi][kk][1], qf[mi][kk][2], qf[mi][kk][3], b10, b11);
                }
            }
        }

        // ---- causal mask (last two kv tiles only) ----
        if (kvb >= 2 * qblk) {
#pragma unroll
            for (int mi = 0; mi < 2; mi++) {
                int rowm = qblk * 128 + 32 * w + 16 * mi + gr;
#pragma unroll
                for (int j = 0; j < 8; j++) {
                    int colb = kvb * 64 + 8 * j + 2 * gc;
                    if (colb     > rowm)     s[mi][j][0] = -1e30f;
                    if (colb + 1 > rowm)     s[mi][j][1] = -1e30f;
                    if (colb     > rowm + 8) s[mi][j][2] = -1e30f;
                    if (colb + 1 > rowm + 8) s[mi][j][3] = -1e30f;
                }
            }
        }

        // ---- online softmax (log2 domain); l kept per-lane ----
        uint32_t ph[2][8][2];
#pragma unroll
        for (int mi = 0; mi < 2; mi++) {
            float mt0 = -1e30f, mt1 = -1e30f;
#pragma unroll
            for (int j = 0; j < 8; j++) {
                mt0 = fmaxf(mt0, fmaxf(s[mi][j][0], s[mi][j][1]));
                mt1 = fmaxf(mt1, fmaxf(s[mi][j][2], s[mi][j][3]));
            }
            // packed half2 quad-reduce of (mt0, mt1)
            {
                uint32_t mp = pack_h2(mt0, mt1);
                __half2 hv = *reinterpret_cast<__half2*>(&mp);
                uint32_t r1 = __shfl_xor_sync(0xffffffffu, mp, 1);
                hv = __hmax2(hv, *reinterpret_cast<__half2*>(&r1));
                uint32_t mp2 = *reinterpret_cast<uint32_t*>(&hv);
                uint32_t r2 = __shfl_xor_sync(0xffffffffu, mp2, 2);
                hv = __hmax2(hv, *reinterpret_cast<__half2*>(&r2));
                mt0 = __low2float(hv);
                mt1 = __high2float(hv);
            }

            const float mn0 = fmaxf(mm[mi][0], mt0);
            const float mn1 = fmaxf(mm[mi][1], mt1);
            float ls0 = 0.f, ls1 = 0.f;
#pragma unroll
            for (int j = 0; j < 8; j++) {
                uint32_t h0 = ex2_h2(pack_h2(s[mi][j][0] - mn0, s[mi][j][1] - mn0));
                uint32_t h1 = ex2_h2(pack_h2(s[mi][j][2] - mn1, s[mi][j][3] - mn1));
                ph[mi][j][0] = h0;
                ph[mi][j][1] = h1;
                float2 f0 = __half22float2(*reinterpret_cast<__half2*>(&h0));
                float2 f1 = __half22float2(*reinterpret_cast<__half2*>(&h1));
                ls0 += f0.x + f0.y;
                ls1 += f1.x + f1.y;
            }

            // warp-voted rescale skip; l stays per-lane (no shuffles here)
            bool no_rescale = (mn0 == mm[mi][0]) && (mn1 == mm[mi][1]);
            if (__all_sync(0xffffffffu, no_rescale)) {
                ll[mi][0] += ls0;
                ll[mi][1] += ls1;
            } else {
                const float al0 = exp2f(mm[mi][0] - mn0);
                const float al1 = exp2f(mm[mi][1] - mn1);
                ll[mi][0] = ll[mi][0] * al0 + ls0;
                ll[mi][1] = ll[mi][1] * al1 + ls1;
                mm[mi][0] = mn0;
                mm[mi][1] = mn1;
#pragma unroll
                for (int j = 0; j < 8; j++) {
                    o[mi][j][0] *= al0; o[mi][j][1] *= al0;
                    o[mi][j][2] *= al1; o[mi][j][3] *= al1;
                }
            }
        }

        // ---- PV: ph pairs ARE the fp16 A-frags ----
#pragma unroll
        for (int kk = 0; kk < 4; kk++) {
#pragma unroll
            for (int c = 0; c < 4; c++) {
                int kvrow = kk * 16 + ((lane >> 3) & 1) * 8 + (lane & 7);
                int dcol  = c * 16 + lhi8;
                uint32_t addr = vbase + ((uint32_t)kvrow * 72u + dcol) * 2u;
                uint32_t b00, b01, b10, b11;
                ldsm_x4_trans(b00, b01, b10, b11, addr);
#pragma unroll
                for (int mi = 0; mi < 2; mi++) {
                    mma_f16(o[mi][2 * c][0], o[mi][2 * c][1], o[mi][2 * c][2], o[mi][2 * c][3],
                            ph[mi][2 * kk][0], ph[mi][2 * kk][1],
                            ph[mi][2 * kk + 1][0], ph[mi][2 * kk + 1][1], b00, b01);
                    mma_f16(o[mi][2 * c + 1][0], o[mi][2 * c + 1][1],
                            o[mi][2 * c + 1][2], o[mi][2 * c + 1][3],
                            ph[mi][2 * kk][0], ph[mi][2 * kk][1],
                            ph[mi][2 * kk + 1][0], ph[mi][2 * kk + 1][1], b10, b11);
                }
            }
        }

        // ---- next tile's cp.async must land before anyone reads it ----
        CP_WAIT(0);
        __syncthreads();
    }

    // ---- final l quad-reduction + normalize + write fp16 ----
#pragma unroll
    for (int mi = 0; mi < 2; mi++) {
        float l0 = ll[mi][0], l1 = ll[mi][1];
        l0 += __shfl_xor_sync(0xffffffffu, l0, 1);
        l0 += __shfl_xor_sync(0xffffffffu, l0, 2);
        l1 += __shfl_xor_sync(0xffffffffu, l1, 1);
        l1 += __shfl_xor_sync(0xffffffffu, l1, 2);
        const float il0 = 1.f / l0;
        const float il1 = 1.f / l1;
        const int row0 = qblk * 128 + 32 * w + 16 * mi + gr;
        __half* op0 = out + (size_t)(b * S_ + row0) * C_ + h * 64;
        __half* op1 = out + (size_t)(b * S_ + row0 + 8) * C_ + h * 64;
#pragma unroll
        for (int j2 = 0; j2 < 8; j2++) {
            int d0 = 8 * j2 + 2 * gc;
            *(uint32_t*)&op0[d0] = pack_h2(o[mi][j2][0] * il0, o[mi][j2][1] * il0);
            *(uint32_t*)&op1[d0] = pack_h2(o[mi][j2][2] * il1, o[mi][j2][3] * il1);
        }
    }
}

// ---------------------------------------------------------------------------
extern "C" void kernel_launch(void* const* d_in, const int* in_sizes, int n_in,
                              void* d_out, int out_size)
{
    const float* x      = (const float*)d_in[0];
    const float* qkv_w  = (const float*)d_in[1];
    const float* qkv_b  = (const float*)d_in[2];
    const float* proj_w = (const float*)d_in[3];
    const float* proj_b = (const float*)d_in[4];
    float* out = (float*)d_out;

    __half *xh, *wh, *pwh, *qkvh, *atth;
    cudaGetSymbolAddress((void**)&xh,   g_xh);
    cudaGetSymbolAddress((void**)&wh,   g_wh);
    cudaGetSymbolAddress((void**)&pwh,  g_pwh);
    cudaGetSymbolAddress((void**)&qkvh, g_qkvh);
    cudaGetSymbolAddress((void**)&atth, g_atth);

    const int ASM = 4 * 64 * 72 * 2;   // 73,728 B (ping-pong K+V)
    cudaFuncSetAttribute((const void*)attn_f16,
                         cudaFuncAttributeMaxDynamicSharedMemorySize, ASM);

    // merged fp16 conversion (one launch)
    F2HArgs fa;
    fa.s0 = x;      fa.d0 = xh;  fa.n0 = M_ * C_;
    fa.s1 = qkv_w;  fa.d1 = wh;  fa.n1 = 3 * C_ * C_;
    fa.s2 = proj_w; fa.d2 = pwh; fa.n2 = C_ * C_;
    const int total = fa.n0 + fa.n1 + fa.n2;
    f2h_all<<<total / 2048, 256>>>(fa);

    // QKV: [8192,1024] x [3072,1024]^T -> fp16
    gemm_hmma<__half><<<dim3(3072 / 128, M_ / 128), 128>>>(xh, wh, qkv_b, qkvh, 3 * C_);
    // Attention (fp16 in/out), Q tile 128, cp.async ping-pong KV
    attn_f16<<<dim3(S_ / 128, B_ * H_), 128, ASM>>>(qkvh, atth);
    // Proj: [8192,1024] x [1024,1024]^T -> fp32 out
    gemm_hmma<float><<<dim3(C_ / 128, M_ / 128), 128>>>(atth, pwh, proj_b, out, C_);
}